// round 1
// baseline (speedup 1.0000x reference)
#include <cuda_runtime.h>
#include <cuda_bf16.h>
#include <cstdint>
#include <cmath>

// Problem constants
#define BB   64      // batch
#define TT   1024    // timesteps
#define DD   512     // input dim
#define HH   512     // hidden dim
#define G4   2048    // 4*H

// ---------------- scratch (device globals; no allocation allowed) ----------------
__device__ float g_xp[(size_t)TT * BB * G4];   // [T][B][4H]  (512 MB)
__device__ float g_h[2][(size_t)BB * HH];      // double-buffered h, [buf][B][H]
__device__ unsigned int g_bar;                 // grid barrier counter

// =====================================================================
// Phase 1: xproj GEMM.  M = B*T = 65536 rows of x ([65536][512]),
// N = 2048 (gate-major columns), K = 512.
// Block tile 64x64, K-tile 16, 256 threads, 4x4 microtile.
// Each N-block lies entirely inside one gate (512 % 64 == 0).
// Output scattered to g_xp[t][b][g*512+col].
// =====================================================================
__global__ void __launch_bounds__(256) xproj_gemm(
    const float* __restrict__ x,
    const float* __restrict__ Wc, const float* __restrict__ Wi,
    const float* __restrict__ Wf, const float* __restrict__ Wo,
    const float* __restrict__ bc, const float* __restrict__ bi,
    const float* __restrict__ bf, const float* __restrict__ bo)
{
    __shared__ float As[16][68];   // [k][m], padded
    __shared__ float Bs[16][64];   // [k][n]

    const int tid = threadIdx.x;
    const int n0  = blockIdx.x * 64;          // 0..2047
    const int g   = n0 >> 9;                  // gate index 0..3
    const int col0 = n0 & 511;                // column within gate
    const int m0  = blockIdx.y * 64;

    const float* Wg = (g == 0) ? Wc : (g == 1) ? Wi : (g == 2) ? Wf : Wo;
    const float* bg = (g == 0) ? bc : (g == 1) ? bi : (g == 2) ? bf : bo;

    const int tx = tid & 15;      // 0..15 -> n
    const int ty = tid >> 4;      // 0..15 -> m

    float acc[4][4];
#pragma unroll
    for (int u = 0; u < 4; u++)
#pragma unroll
        for (int v = 0; v < 4; v++) acc[u][v] = 0.f;

    const int arow = tid >> 2;        // 0..63
    const int akq  = tid & 3;         // 0..3 (float4 chunk within 16-wide k tile)
    const int bkr  = tid >> 4;        // 0..15
    const int bnq  = tid & 15;        // 0..15

    for (int k0 = 0; k0 < DD; k0 += 16) {
        // load A tile (transposed into As[k][m])
        {
            const float4 v = *reinterpret_cast<const float4*>(
                x + (size_t)(m0 + arow) * DD + k0 + akq * 4);
            As[akq * 4 + 0][arow] = v.x;
            As[akq * 4 + 1][arow] = v.y;
            As[akq * 4 + 2][arow] = v.z;
            As[akq * 4 + 3][arow] = v.w;
        }
        // load B tile
        {
            const float4 v = *reinterpret_cast<const float4*>(
                Wg + (size_t)(k0 + bkr) * HH + col0 + bnq * 4);
            *reinterpret_cast<float4*>(&Bs[bkr][bnq * 4]) = v;
        }
        __syncthreads();
#pragma unroll
        for (int kk = 0; kk < 16; kk++) {
            const float4 a4 = *reinterpret_cast<const float4*>(&As[kk][ty * 4]);
            const float4 b4 = *reinterpret_cast<const float4*>(&Bs[kk][tx * 4]);
            const float av[4] = {a4.x, a4.y, a4.z, a4.w};
            const float bv[4] = {b4.x, b4.y, b4.z, b4.w};
#pragma unroll
            for (int u = 0; u < 4; u++)
#pragma unroll
                for (int v = 0; v < 4; v++)
                    acc[u][v] = fmaf(av[u], bv[v], acc[u][v]);
        }
        __syncthreads();
    }

    // epilogue: add bias, scatter to [T][B][4H]
    const float4 bb4 = *reinterpret_cast<const float4*>(bg + col0 + tx * 4);
#pragma unroll
    for (int u = 0; u < 4; u++) {
        const int r  = m0 + ty * 4 + u;       // row in [B*T]
        const int b_ = r >> 10;               // batch
        const int t_ = r & 1023;              // time
        float4 o;
        o.x = acc[u][0] + bb4.x;
        o.y = acc[u][1] + bb4.y;
        o.z = acc[u][2] + bb4.z;
        o.w = acc[u][3] + bb4.w;
        *reinterpret_cast<float4*>(
            g_xp + ((size_t)t_ * BB + b_) * G4 + g * HH + col0 + tx * 4) = o;
    }
}

// =====================================================================
// Phase 2: persistent recurrence kernel.
// Grid: 128 blocks = 32 j-slices x 4 b-slices. Block owns 16 hidden
// units (x4 gates = 64 U columns, resident in smem for all T) and
// 16 batches. One thread = one (b, j) pair; c-state in a register.
// Per step: stage h-slice (L2, __ldcg) -> 4 dot products of length 512
// -> gates -> write h to double buffer + output -> atomic grid barrier.
// =====================================================================
#define NBLK   128
#define UPITCH 516              // padded row pitch (floats), 16B-aligned, bank-staggered
#define SMEM_FLOATS (64 * UPITCH + 16 * UPITCH)
#define SMEM_BYTES  (SMEM_FLOATS * 4)

__device__ __forceinline__ float sigf(float v) {
    return 1.f / (1.f + __expf(-v));
}

__global__ void __launch_bounds__(256, 1) lstm_recur(
    const float* __restrict__ Uc, const float* __restrict__ Ui,
    const float* __restrict__ Uf, const float* __restrict__ Uo,
    float* __restrict__ out)
{
    extern __shared__ float sm[];
    float* Us  = sm;                 // [64][UPITCH]  U columns, k-contiguous
    float* hsm = sm + 64 * UPITCH;   // [16][UPITCH]  h slice, k-contiguous per batch

    const int tid = threadIdx.x;
    const int jb = blockIdx.x & 31;
    const int bbk = blockIdx.x >> 5;
    const int j0 = jb * 16;
    const int b0 = bbk * 16;

    // ---- load U slice into smem (once) ----
    {
        const int col = tid >> 2;            // 0..63
        const int kc  = (tid & 3) * 128;
        const int g   = col >> 4;
        const int jc  = col & 15;
        const float* Ug = (g == 0) ? Uc : (g == 1) ? Ui : (g == 2) ? Uf : Uo;
        const float* src = Ug + j0 + jc;
        float* dst = Us + col * UPITCH;
        for (int k = kc; k < kc + 128; k++)
            dst[k] = src[(size_t)k * HH];
    }

    const int bi_ = tid >> 4;     // 0..15 local batch
    const int ji  = tid & 15;     // 0..15 local hidden unit
    const int b   = b0 + bi_;
    const int j   = j0 + ji;

    const float* ucp = Us + (0  + ji) * UPITCH;
    const float* uip = Us + (16 + ji) * UPITCH;
    const float* ufp = Us + (32 + ji) * UPITCH;
    const float* uop = Us + (48 + ji) * UPITCH;
    float* hrow = hsm + bi_ * UPITCH;

    float cst = 0.f;
    unsigned cur = 0;

    __syncthreads();

    for (int t = 0; t < TT; t++) {
        // prefetch xproj for this (b, j) — long latency, overlapped below
        const float* xpp = g_xp + ((size_t)t * BB + b) * G4 + j;
        const float xc = xpp[0];
        const float xi = xpp[HH];
        const float xf = xpp[2 * HH];
        const float xo = xpp[3 * HH];

        float ac = 0.f, ai = 0.f, af = 0.f, ao = 0.f;

        if (t > 0) {
            // stage h slice [16 x 512] from global double buffer (L2, no L1)
            const float* hb = g_h[cur] + (size_t)b0 * HH;
#pragma unroll
            for (int q = 0; q < 8; q++) {
                const int e   = q * 256 + tid;      // 0..2047 float4s
                const int row = e >> 7;
                const int c4  = (e & 127) * 4;
                const float4 v = __ldcg(reinterpret_cast<const float4*>(hb + row * HH + c4));
                *reinterpret_cast<float4*>(hsm + row * UPITCH + c4) = v;
            }
            __syncthreads();

#pragma unroll 4
            for (int k = 0; k < HH; k += 4) {
                const float4 hv = *reinterpret_cast<const float4*>(hrow + k);
                const float4 u0 = *reinterpret_cast<const float4*>(ucp + k);
                ac = fmaf(hv.x, u0.x, ac); ac = fmaf(hv.y, u0.y, ac);
                ac = fmaf(hv.z, u0.z, ac); ac = fmaf(hv.w, u0.w, ac);
                const float4 u1 = *reinterpret_cast<const float4*>(uip + k);
                ai = fmaf(hv.x, u1.x, ai); ai = fmaf(hv.y, u1.y, ai);
                ai = fmaf(hv.z, u1.z, ai); ai = fmaf(hv.w, u1.w, ai);
                const float4 u2 = *reinterpret_cast<const float4*>(ufp + k);
                af = fmaf(hv.x, u2.x, af); af = fmaf(hv.y, u2.y, af);
                af = fmaf(hv.z, u2.z, af); af = fmaf(hv.w, u2.w, af);
                const float4 u3 = *reinterpret_cast<const float4*>(uop + k);
                ao = fmaf(hv.x, u3.x, ao); ao = fmaf(hv.y, u3.y, ao);
                ao = fmaf(hv.z, u3.z, ao); ao = fmaf(hv.w, u3.w, ao);
            }
        }

        const float a  = tanhf(xc + ac);
        const float ig = sigf(xi + ai);
        const float fg = sigf(xf + af);
        const float og = sigf(xo + ao);
        cst = ig * a + fg * cst;
        const float hval = og * tanhf(cst);

        out[((size_t)b * TT + t) * HH + j] = hval;
        g_h[cur ^ 1][(size_t)b * HH + j] = hval;

        // ---- grid barrier ----
        __threadfence();           // make this thread's h writes L2-visible
        __syncthreads();           // everyone's fence done before tid0 signals
        if (tid == 0) {
            atomicAdd(&g_bar, 1u);
            const unsigned tgt = (unsigned)gridDim.x * (unsigned)(t + 1);
            while (*reinterpret_cast<volatile unsigned*>(&g_bar) < tgt) { }
        }
        __syncthreads();
        cur ^= 1;
    }
}

// =====================================================================
// launch
// =====================================================================
extern "C" void kernel_launch(void* const* d_in, const int* in_sizes, int n_in,
                              void* d_out, int out_size)
{
    const float* x  = (const float*)d_in[0];
    const float* Wc = (const float*)d_in[1];
    const float* Wi = (const float*)d_in[2];
    const float* Wf = (const float*)d_in[3];
    const float* Wo = (const float*)d_in[4];
    const float* Uc = (const float*)d_in[5];
    const float* Ui = (const float*)d_in[6];
    const float* Uf = (const float*)d_in[7];
    const float* Uo = (const float*)d_in[8];
    const float* bc = (const float*)d_in[9];
    const float* bi = (const float*)d_in[10];
    const float* bf = (const float*)d_in[11];
    const float* bo = (const float*)d_in[12];
    float* out = (float*)d_out;

    cudaFuncSetAttribute(lstm_recur,
                         cudaFuncAttributeMaxDynamicSharedMemorySize, SMEM_BYTES);

    // reset grid-barrier counter (graph-capturable memset node)
    void* barp = nullptr;
    cudaGetSymbolAddress(&barp, g_bar);
    cudaMemsetAsync(barp, 0, sizeof(unsigned int), 0);

    dim3 g1(G4 / 64, (BB * TT) / 64);   // 32 x 1024
    xproj_gemm<<<g1, 256>>>(x, Wc, Wi, Wf, Wo, bc, bi, bf, bo);

    lstm_recur<<<NBLK, 256, SMEM_BYTES>>>(Uc, Ui, Uf, Uo, out);
}

// round 5
// speedup vs baseline: 1.3141x; 1.3141x over previous
#include <cuda_runtime.h>
#include <cuda_bf16.h>
#include <cstdint>
#include <cmath>

#define BB   64      // batch
#define TT   1024    // timesteps
#define DD   512     // input dim
#define HH   512     // hidden dim
#define G4   2048    // 4*H
#define NBLK 128     // persistent blocks

// ---------------- scratch ----------------
__device__ float g_xp[(size_t)TT * BB * G4];   // [T][B][4H]
__device__ float g_h[2][(size_t)BB * HH];      // double-buffered h
__device__ unsigned int g_bar;

// =====================================================================
// Phase 1: xproj GEMM (round-1 proven version).
// =====================================================================
__global__ void __launch_bounds__(256) xproj_gemm(
    const float* __restrict__ x,
    const float* __restrict__ Wc, const float* __restrict__ Wi,
    const float* __restrict__ Wf, const float* __restrict__ Wo,
    const float* __restrict__ bc, const float* __restrict__ bi,
    const float* __restrict__ bf, const float* __restrict__ bo)
{
    __shared__ float As[16][68];
    __shared__ float Bs[16][64];

    const int tid = threadIdx.x;
    const int n0  = blockIdx.x * 64;
    const int g   = n0 >> 9;
    const int col0 = n0 & 511;
    const int m0  = blockIdx.y * 64;

    const float* Wg = (g == 0) ? Wc : (g == 1) ? Wi : (g == 2) ? Wf : Wo;
    const float* bg = (g == 0) ? bc : (g == 1) ? bi : (g == 2) ? bf : bo;

    const int tx = tid & 15;
    const int ty = tid >> 4;

    float acc[4][4];
#pragma unroll
    for (int u = 0; u < 4; u++)
#pragma unroll
        for (int v = 0; v < 4; v++) acc[u][v] = 0.f;

    const int arow = tid >> 2;
    const int akq  = tid & 3;
    const int bkr  = tid >> 4;
    const int bnq  = tid & 15;

    for (int k0 = 0; k0 < DD; k0 += 16) {
        {
            const float4 v = *reinterpret_cast<const float4*>(
                x + (size_t)(m0 + arow) * DD + k0 + akq * 4);
            As[akq * 4 + 0][arow] = v.x;
            As[akq * 4 + 1][arow] = v.y;
            As[akq * 4 + 2][arow] = v.z;
            As[akq * 4 + 3][arow] = v.w;
        }
        {
            const float4 v = *reinterpret_cast<const float4*>(
                Wg + (size_t)(k0 + bkr) * HH + col0 + bnq * 4);
            *reinterpret_cast<float4*>(&Bs[bkr][bnq * 4]) = v;
        }
        __syncthreads();
#pragma unroll
        for (int kk = 0; kk < 16; kk++) {
            const float4 a4 = *reinterpret_cast<const float4*>(&As[kk][ty * 4]);
            const float4 b4 = *reinterpret_cast<const float4*>(&Bs[kk][tx * 4]);
            const float av[4] = {a4.x, a4.y, a4.z, a4.w};
            const float bv[4] = {b4.x, b4.y, b4.z, b4.w};
#pragma unroll
            for (int u = 0; u < 4; u++)
#pragma unroll
                for (int v = 0; v < 4; v++)
                    acc[u][v] = fmaf(av[u], bv[v], acc[u][v]);
        }
        __syncthreads();
    }

    const float4 bb4 = *reinterpret_cast<const float4*>(bg + col0 + tx * 4);
#pragma unroll
    for (int u = 0; u < 4; u++) {
        const int r  = m0 + ty * 4 + u;
        const int b_ = r >> 10;
        const int t_ = r & 1023;
        float4 o;
        o.x = acc[u][0] + bb4.x;
        o.y = acc[u][1] + bb4.y;
        o.z = acc[u][2] + bb4.z;
        o.w = acc[u][3] + bb4.w;
        *reinterpret_cast<float4*>(
            g_xp + ((size_t)t_ * BB + b_) * G4 + g * HH + col0 + tx * 4) = o;
    }
}

// =====================================================================
// Phase 2: persistent recurrence (round-3 structure, double-buffered h,
// ROUND-1 PROVEN volatile barrier spin — no inline asm).
// 128 blocks = 4 batch-groups(16) x 32 j-groups(16 cols x 4 gates).
// U slice [512][64] resident in smem. h staged transposed hs[k][b].
// 128 threads = 2 k-halves x (4 ty x 16 tx), 4x4 register microtile,
// smem combine, gate math (2 pairs/thread, c in registers).
// =====================================================================
#define THR     128
#define HSP     20
#define SMEM_FLOATS (512 * 64 + 512 * HSP + 16 * 68)
#define SMEM_BYTES  (SMEM_FLOATS * 4)

__device__ __forceinline__ float sigf(float v) {
    return 1.f / (1.f + __expf(-v));
}

__global__ void __launch_bounds__(THR, 1) lstm_recur(
    const float* __restrict__ Uc, const float* __restrict__ Ui,
    const float* __restrict__ Uf, const float* __restrict__ Uo,
    float* __restrict__ out)
{
    extern __shared__ float sm[];
    float* Us  = sm;                    // [512][64] k-major
    float* hs  = sm + 512 * 64;         // [512][HSP], cols 0..15 used
    float* Cmb = hs + 512 * HSP;        // [16][68]

    const int tid  = threadIdx.x;
    const int bx   = blockIdx.x;
    const int bgrp = bx >> 5;
    const int jgrp = bx & 31;
    const int b0   = bgrp * 16;
    const int jcol0 = jgrp * 16;

    // ---- load resident U slice: Us[k][gate*16+jc] = Ug[k][jcol0+jc] ----
    {
        const int c4   = tid & 15;
        const int gate = c4 >> 2;
        const float* Ug = (gate == 0) ? Uc : (gate == 1) ? Ui
                        : (gate == 2) ? Uf : Uo;
        const float* src = Ug + jcol0 + (c4 & 3) * 4;
        for (int k = tid >> 4; k < 512; k += 8)
            *reinterpret_cast<float4*>(&Us[k * 64 + c4 * 4]) =
                *reinterpret_cast<const float4*>(src + (size_t)k * HH);
    }

    const int kh    = tid >> 6;
    const int lcl   = tid & 63;
    const int txl   = lcl & 15;
    const int tyl   = lcl >> 4;
    const int kbase = kh * 256;

    const int sb = tid & 15;
    const int sq = tid >> 4;

    const int gjb   = tid >> 4;
    const int gj    = tid & 15;
    const int gb0   = b0 + gjb;
    const int gb1   = gb0 + 8;
    const int jglob = jcol0 + gj;

    const float4* Us4 = reinterpret_cast<const float4*>(Us);
    float4*       C4  = reinterpret_cast<float4*>(Cmb);

    float cst0 = 0.f, cst1 = 0.f;

    __syncthreads();

    for (int t = 0; t < TT; t++) {
        const float* xp0 = g_xp + ((size_t)t * BB + gb0) * G4 + jglob;
        const float* xp1 = g_xp + ((size_t)t * BB + gb1) * G4 + jglob;
        const float x0c = xp0[0];
        const float x0i = xp0[HH];
        const float x0f = xp0[2 * HH];
        const float x0o = xp0[3 * HH];
        const float x1c = xp1[0];
        const float x1i = xp1[HH];
        const float x1f = xp1[2 * HH];
        const float x1o = xp1[3 * HH];

        float s0c = 0.f, s0i = 0.f, s0f = 0.f, s0o = 0.f;
        float s1c = 0.f, s1i = 0.f, s1f = 0.f, s1o = 0.f;

        if (t > 0) {
            // ---- stage h(t-1) from READ buffer, transposed ----
            const float* hb = g_h[t & 1] + (size_t)(b0 + sb) * HH;
#pragma unroll
            for (int it = 0; it < 16; it++) {
                const int kb = sq * 4 + it * 32;
                const float4 v = __ldcg(reinterpret_cast<const float4*>(hb + kb));
                hs[(kb + 0) * HSP + sb] = v.x;
                hs[(kb + 1) * HSP + sb] = v.y;
                hs[(kb + 2) * HSP + sb] = v.z;
                hs[(kb + 3) * HSP + sb] = v.w;
            }
            __syncthreads();

            float acc[4][4];
#pragma unroll
            for (int i = 0; i < 4; i++)
#pragma unroll
                for (int j = 0; j < 4; j++) acc[i][j] = 0.f;

#pragma unroll 4
            for (int k = kbase; k < kbase + 256; k++) {
                const float4 hv = *reinterpret_cast<const float4*>(
                    &hs[k * HSP + tyl * 4]);
                const float4 uv = Us4[k * 16 + txl];
                const float av[4] = {hv.x, hv.y, hv.z, hv.w};
                const float bv[4] = {uv.x, uv.y, uv.z, uv.w};
#pragma unroll
                for (int i = 0; i < 4; i++)
#pragma unroll
                    for (int j = 0; j < 4; j++)
                        acc[i][j] = fmaf(av[i], bv[j], acc[i][j]);
            }

            if (kh == 0) {
#pragma unroll
                for (int i = 0; i < 4; i++)
                    C4[(tyl * 4 + i) * 17 + txl] =
                        make_float4(acc[i][0], acc[i][1], acc[i][2], acc[i][3]);
            }
            __syncthreads();
            if (kh == 1) {
#pragma unroll
                for (int i = 0; i < 4; i++) {
                    float4 v = C4[(tyl * 4 + i) * 17 + txl];
                    v.x += acc[i][0];
                    v.y += acc[i][1];
                    v.z += acc[i][2];
                    v.w += acc[i][3];
                    C4[(tyl * 4 + i) * 17 + txl] = v;
                }
            }
            __syncthreads();

            s0c = Cmb[gjb * 68 + gj];
            s0i = Cmb[gjb * 68 + 16 + gj];
            s0f = Cmb[gjb * 68 + 32 + gj];
            s0o = Cmb[gjb * 68 + 48 + gj];
            s1c = Cmb[(gjb + 8) * 68 + gj];
            s1i = Cmb[(gjb + 8) * 68 + 16 + gj];
            s1f = Cmb[(gjb + 8) * 68 + 32 + gj];
            s1o = Cmb[(gjb + 8) * 68 + 48 + gj];
        }

        float* hw = g_h[(t + 1) & 1];   // WRITE buffer

        {
            const float a  = tanhf(x0c + s0c);
            const float ig = sigf(x0i + s0i);
            const float fg = sigf(x0f + s0f);
            const float og = sigf(x0o + s0o);
            cst0 = ig * a + fg * cst0;
            const float hval = og * tanhf(cst0);
            out[((size_t)gb0 * TT + t) * HH + jglob] = hval;
            hw[(size_t)gb0 * HH + jglob] = hval;
        }
        {
            const float a  = tanhf(x1c + s1c);
            const float ig = sigf(x1i + s1i);
            const float fg = sigf(x1f + s1f);
            const float og = sigf(x1o + s1o);
            cst1 = ig * a + fg * cst1;
            const float hval = og * tanhf(cst1);
            out[((size_t)gb1 * TT + t) * HH + jglob] = hval;
            hw[(size_t)gb1 * HH + jglob] = hval;
        }

        // ---- grid barrier (round-1 proven volatile spin) ----
        __threadfence();
        __syncthreads();
        if (tid == 0) {
            atomicAdd(&g_bar, 1u);
            const unsigned tgt = (unsigned)(t + 1) * (unsigned)NBLK;
            while (*reinterpret_cast<volatile unsigned*>(&g_bar) < tgt) { }
        }
        __syncthreads();
    }
}

// =====================================================================
extern "C" void kernel_launch(void* const* d_in, const int* in_sizes, int n_in,
                              void* d_out, int out_size)
{
    const float* x  = (const float*)d_in[0];
    const float* Wc = (const float*)d_in[1];
    const float* Wi = (const float*)d_in[2];
    const float* Wf = (const float*)d_in[3];
    const float* Wo = (const float*)d_in[4];
    const float* Uc = (const float*)d_in[5];
    const float* Ui = (const float*)d_in[6];
    const float* Uf = (const float*)d_in[7];
    const float* Uo = (const float*)d_in[8];
    const float* bc = (const float*)d_in[9];
    const float* bi = (const float*)d_in[10];
    const float* bf = (const float*)d_in[11];
    const float* bo = (const float*)d_in[12];
    float* out = (float*)d_out;

    cudaFuncSetAttribute(lstm_recur,
                         cudaFuncAttributeMaxDynamicSharedMemorySize, SMEM_BYTES);

    void* barp = nullptr;
    cudaGetSymbolAddress(&barp, g_bar);
    cudaMemsetAsync(barp, 0, sizeof(unsigned int), 0);

    dim3 g1(G4 / 64, (BB * TT) / 64);   // 32 x 1024
    xproj_gemm<<<g1, 256>>>(x, Wc, Wi, Wf, Wo, bc, bi, bf, bo);

    lstm_recur<<<NBLK, THR, SMEM_BYTES>>>(Uc, Ui, Uf, Uo, out);
}